// round 17
// baseline (speedup 1.0000x reference)
#include <cuda_runtime.h>

// Problem constants (fixed shapes)
#define NN   50000
#define EE   640000
#define DIN  64
#define GB_  128
#define GD_  4
#define LB_  256
#define LD_  2
#define GG   1024
#define NBLK 196          // scan blocks: 196*256 >= NN

typedef unsigned long long ull;
typedef unsigned int uint;

// ---------------- device scratch ----------------
__device__ __align__(16) float d_dinv[NN];
__device__ int   d_ideg[NN];
__device__ int   d_off[NN + 1];
__device__ int   d_cursor[NN];
__device__ int   d_bsum[NBLK];
__device__ int   d_srcA[EE];
__device__ int   d_dstA[EE];
__device__ __align__(16) int2  d_csr[EE];      // {src, float_bits(enorm)}
__device__ __align__(16) float d_aggx[(size_t)NN * DIN];
__device__ __align__(16) float d_hw [(size_t)NN * GB_];
__device__ __align__(16) float d_agg[(size_t)NN * GB_];
__device__ __align__(16) float d_stats[2 * GB_];      // zero-init; reset by finalize
__device__ __align__(16) float d_scale[GB_];
__device__ __align__(16) float d_shift[GB_];
__device__ __align__(16) float d_hp[GG * GB_];
__device__ __align__(16) float d_l0[GG * LB_];
__device__ __align__(16) float d_l1[GG * LB_];
__device__ __align__(16) float d_lstats[2 * LB_];     // zero-init; reset by finalize
__device__ __align__(16) float d_lscale[LB_];
__device__ __align__(16) float d_lshift[LB_];
__device__ int d_ctr;     // k_agg finalize ticket
__device__ int d_lctr;    // headgemm finalize ticket
__device__ int d_is64;

// ---------------- helpers ----------------
__device__ __forceinline__ void red_add_v4(float* p, float a, float b, float c, float d) {
    asm volatile("red.global.add.v4.f32 [%0], {%1, %2, %3, %4};"
                 :: "l"(p), "f"(a), "f"(b), "f"(c), "f"(d) : "memory");
}
__device__ __forceinline__ ull ffma2(ull a, ull b, ull c) {
    ull r;
    asm("fma.rn.f32x2 %0, %1, %2, %3;" : "=l"(r) : "l"(a), "l"(b), "l"(c));
    return r;
}
__device__ __forceinline__ float redpair(ull v) {  // lo + hi
    float2 r;
    asm("mov.b64 {%0, %1}, %2;" : "=f"(r.x), "=f"(r.y) : "l"(v));
    return r.x + r.y;
}

// ---------------- preprocessing ----------------
__global__ void k_prep(const void* __restrict__ ei) {
    __shared__ int s64;
    if (threadIdx.x == 0) {
        const int* p32 = (const int*)ei;
        int zeros = 0;
        for (int i = 0; i < 64; i++)
            if (p32[2 * i + 1] == 0) zeros++;
        s64 = (zeros >= 60) ? 1 : 0;
        if (blockIdx.x == 0) d_is64 = s64;
    }
    __syncthreads();
    int e = blockIdx.x * blockDim.x + threadIdx.x;
    if (e < EE) {
        int s, d;
        if (s64) {
            const long long* p = (const long long*)ei;
            s = (int)p[e];
            d = (int)p[EE + e];
        } else {
            const int* p = (const int*)ei;
            s = p[e];
            d = p[EE + e];
        }
        s = min(max(s, 0), NN - 1);
        d = min(max(d, 0), NN - 1);
        d_srcA[e] = s;
        d_dstA[e] = d;
        atomicAdd(&d_ideg[d], 1);
    }
}

// scan pass 1: per-block exclusive scan of ideg; also dinv, ideg reset, hp zero.
__global__ __launch_bounds__(256) void k_scan1() {
    __shared__ int wsum[8];
    int t = threadIdx.x, lane = t & 31, wid = t >> 5;
    int n = blockIdx.x * 256 + t;
    if (n < GG * GB_ / 4) ((float4*)d_hp)[n] = make_float4(0.f, 0.f, 0.f, 0.f);
    int v = 0;
    if (n < NN) {
        v = d_ideg[n];
        d_ideg[n] = 0;                       // reset for next replay
        d_dinv[n] = rsqrtf((float)(1 + v));
    }
    int x = v;
    #pragma unroll
    for (int o = 1; o < 32; o <<= 1) {
        int y = __shfl_up_sync(0xffffffffu, x, o);
        if (lane >= o) x += y;
    }
    if (lane == 31) wsum[wid] = x;
    __syncthreads();
    if (wid == 0 && lane < 8) {
        int y = wsum[lane];
        #pragma unroll
        for (int o = 1; o < 8; o <<= 1) {
            int z = __shfl_up_sync(0xffu, y, o);
            if (lane >= o) y += z;
        }
        wsum[lane] = y;
    }
    __syncthreads();
    int excl = (wid > 0 ? wsum[wid - 1] : 0) + x - v;
    if (n < NN) d_off[n] = excl;
    if (t == 255) d_bsum[blockIdx.x] = wsum[7];
}

// scan pass 2 (merged): each block computes its own prefix of d_bsum, then
// adds it to its local offsets and inits cursor.
__global__ __launch_bounds__(256) void k_scan3() {
    __shared__ int red[8];
    __shared__ int s_prefix;
    int t = threadIdx.x, lane = t & 31, wid = t >> 5;
    int bid = blockIdx.x;
    int v = (t < NBLK && t < bid) ? d_bsum[t] : 0;
    #pragma unroll
    for (int o = 16; o > 0; o >>= 1) v += __shfl_down_sync(0xffffffffu, v, o);
    if (lane == 0) red[wid] = v;
    __syncthreads();
    if (t == 0) {
        int s = 0;
        #pragma unroll
        for (int i = 0; i < 8; i++) s += red[i];
        s_prefix = s;
        if (bid == 0) d_off[NN] = EE;
    }
    __syncthreads();
    int n = bid * 256 + t;
    if (n < NN) {
        int o = d_off[n] + s_prefix;
        d_off[n] = o;
        d_cursor[n] = o;
    }
}

__global__ void k_csr_fill() {
    int e = blockIdx.x * blockDim.x + threadIdx.x;
    if (e < EE) {
        int s = d_srcA[e], d = d_dstA[e];
        int pos = atomicAdd(&d_cursor[d], 1);
        float w = d_dinv[s] * d_dinv[d];
        d_csr[pos] = make_int2(s, __float_as_int(w));
    }
}

// ---------------- layer-0 aggregation on raw x (64 wide, fp32) ----------------
// edge loop unrolled x2 with independent accumulators (doubles gather MLP)
__global__ __launch_bounds__(256) void k_aggx(const float* __restrict__ x) {
    int n = blockIdx.x * 8 + (threadIdx.x >> 5);
    if (n >= NN) return;
    int lane = threadIdx.x & 31;
    float sn = __ldg(&d_dinv[n]);
    float sn2 = sn * sn;
    float2 vs = __ldg((const float2*)(x + (size_t)n * DIN) + lane);
    float2 acca = make_float2(vs.x * sn2, vs.y * sn2);
    float2 accb = make_float2(0.f, 0.f);

    int o0 = __ldg(&d_off[n]), o1 = __ldg(&d_off[n + 1]);
    for (int e = o0; e < o1; e += 2) {
        int2 ea = __ldg(&d_csr[e]);
        bool hb = (e + 1 < o1);
        int2 eb = hb ? __ldg(&d_csr[e + 1]) : make_int2(0, 0);
        float wa = __int_as_float(ea.y);
        float wb = hb ? __int_as_float(eb.y) : 0.f;
        float2 va = __ldg((const float2*)(x + (size_t)ea.x * DIN) + lane);
        float2 vb = __ldg((const float2*)(x + (size_t)eb.x * DIN) + lane);
        acca.x += va.x * wa; acca.y += va.y * wa;
        accb.x += vb.x * wb; accb.y += vb.y * wb;
    }
    acca.x += accb.x; acca.y += accb.y;
    *((float2*)(d_aggx + (size_t)n * DIN) + lane) = acca;
}

// ---------------- node GEMM: out[N,128] = f(in)[N,K] @ W[K,128] ----------------
// K-parity split f32x2 accumulators; h read via natural broadcast LDS.64;
// weights k-pair interleaved (LDS.128 covers 2 cols). FFMA2-pipe-bound. 48KB smem.
template <int K, bool INBN, bool EPI>
__global__ __launch_bounds__(256) void k_gemm(const float* __restrict__ h,
                                              const float* __restrict__ W,
                                              const float* __restrict__ bias,
                                              float* __restrict__ out) {
    extern __shared__ float sm[];
    float2* wt = (float2*)sm;          // [32][128] float2: wt[kk2][c] = (W[2kk2][c], W[2kk2+1][c])
    float*  hs = sm + 32 * 128 * 2;    // [64][64] floats, row-major h chunk
    int t = threadIdx.x;
    int row0 = blockIdx.x * 64;
    int warp = t >> 5, lane = t & 31;
    int wr0 = warp * 8;

    ull acc[8][4] = {};   // [row][col: 2l, 2l+1, 64+2l, 64+2l+1]

    #pragma unroll
    for (int kc = 0; kc < K; kc += 64) {
        if (kc > 0) __syncthreads();
        for (int i = t; i < 1024; i += 256) {
            int kk2 = i >> 5;
            int c4 = (i & 31) * 4;
            float4 lo = *(const float4*)(W + (size_t)(kc + 2 * kk2) * 128 + c4);
            float4 hi = *(const float4*)(W + (size_t)(kc + 2 * kk2 + 1) * 128 + c4);
            *(float4*)&wt[kk2 * 128 + c4]     = make_float4(lo.x, hi.x, lo.y, hi.y);
            *(float4*)&wt[kk2 * 128 + c4 + 2] = make_float4(lo.z, hi.z, lo.w, hi.w);
        }
        for (int i = t; i < 1024; i += 256) {
            int row = i >> 4;
            int q = i & 15;
            int grow = row0 + row;
            float4 v = make_float4(0.f, 0.f, 0.f, 0.f);
            if (grow < NN) {
                v = *(const float4*)(h + (size_t)grow * K + kc + 4 * q);
                if (INBN) {
                    float4 sc = *(const float4*)&d_scale[kc + 4 * q];
                    float4 sh = *(const float4*)&d_shift[kc + 4 * q];
                    v.x = fmaxf(v.x * sc.x + sh.x, 0.0f);
                    v.y = fmaxf(v.y * sc.y + sh.y, 0.0f);
                    v.z = fmaxf(v.z * sc.z + sh.z, 0.0f);
                    v.w = fmaxf(v.w * sc.w + sh.w, 0.0f);
                }
            }
            *(float4*)&hs[row * 64 + 4 * q] = v;
        }
        __syncthreads();

        #pragma unroll 2
        for (int kk2 = 0; kk2 < 32; kk2++) {
            ulonglong2 wab = *(const ulonglong2*)&wt[kk2 * 128 + 2 * lane];        // cols 2l, 2l+1
            ulonglong2 wcd = *(const ulonglong2*)&wt[kk2 * 128 + 64 + 2 * lane];   // cols 64+2l, 64+2l+1
            #pragma unroll
            for (int r = 0; r < 8; r++) {
                ull hv = *(const ull*)&hs[(wr0 + r) * 64 + 2 * kk2];   // broadcast (h_even, h_odd)
                acc[r][0] = ffma2(hv, wab.x, acc[r][0]);
                acc[r][1] = ffma2(hv, wab.y, acc[r][1]);
                acc[r][2] = ffma2(hv, wcd.x, acc[r][2]);
                acc[r][3] = ffma2(hv, wcd.y, acc[r][3]);
            }
        }
    }

    float2 bb0, bb1;
    if (EPI) {
        bb0 = *(const float2*)&bias[2 * lane];
        bb1 = *(const float2*)&bias[64 + 2 * lane];
    }
    #pragma unroll
    for (int r = 0; r < 8; r++) {
        int grow = row0 + wr0 + r;
        if (grow < NN) {
            float2 v0 = make_float2(redpair(acc[r][0]), redpair(acc[r][1]));
            float2 v1 = make_float2(redpair(acc[r][2]), redpair(acc[r][3]));
            if (EPI) {
                v0.x = fmaxf(v0.x + bb0.x, 0.0f); v0.y = fmaxf(v0.y + bb0.y, 0.0f);
                v1.x = fmaxf(v1.x + bb1.x, 0.0f); v1.y = fmaxf(v1.y + bb1.y, 0.0f);
            }
            float* o = out + (size_t)grow * 128;
            *(float2*)(o + 2 * lane)      = v0;
            *(float2*)(o + 64 + 2 * lane) = v1;
        }
    }
}

// ---------------- CSR aggregation (128-wide) + BN stats + last-block finalize ----------------
// edge loop unrolled x2 with independent accumulators (doubles gather MLP)
__global__ __launch_bounds__(256) void k_agg(const float* __restrict__ bias,
                                             const float* __restrict__ gamma,
                                             const float* __restrict__ beta) {
    __shared__ float ss[128], sq[128];
    __shared__ int s_last;
    int t = threadIdx.x, lane = t & 31, warp = t >> 5;
    if (t < 128) { ss[t] = 0.f; sq[t] = 0.f; }
    __syncthreads();
    float4 bias4 = __ldg((const float4*)bias + lane);
    float4 sum4 = {0, 0, 0, 0}, sq4 = {0, 0, 0, 0};

    int n0 = (blockIdx.x * 8 + warp) * 8;
    for (int j = 0; j < 8; j++) {
        int n = n0 + j;
        if (n >= NN) break;
        float4 acca = bias4;
        float4 accb = {0, 0, 0, 0};
        int o0 = __ldg(&d_off[n]), o1 = __ldg(&d_off[n + 1]);
        for (int e = o0; e < o1; e += 2) {
            int2 ea = __ldg(&d_csr[e]);
            bool hb = (e + 1 < o1);
            int2 eb = hb ? __ldg(&d_csr[e + 1]) : make_int2(0, 0);
            float wa = __int_as_float(ea.y);
            float wb = hb ? __int_as_float(eb.y) : 0.f;
            float4 va = __ldg((const float4*)(d_hw + (size_t)ea.x * 128) + lane);
            float4 vb = __ldg((const float4*)(d_hw + (size_t)eb.x * 128) + lane);
            acca.x += va.x * wa; acca.y += va.y * wa; acca.z += va.z * wa; acca.w += va.w * wa;
            accb.x += vb.x * wb; accb.y += vb.y * wb; accb.z += vb.z * wb; accb.w += vb.w * wb;
        }
        float sn = __ldg(&d_dinv[n]);
        float sn2 = sn * sn;
        float4 vs = *((const float4*)(d_hw + (size_t)n * 128) + lane);
        float4 acc;
        acc.x = acca.x + accb.x + vs.x * sn2;
        acc.y = acca.y + accb.y + vs.y * sn2;
        acc.z = acca.z + accb.z + vs.z * sn2;
        acc.w = acca.w + accb.w + vs.w * sn2;

        *((float4*)(d_agg + (size_t)n * 128) + lane) = acc;
        sum4.x += acc.x; sum4.y += acc.y; sum4.z += acc.z; sum4.w += acc.w;
        sq4.x += acc.x * acc.x; sq4.y += acc.y * acc.y;
        sq4.z += acc.z * acc.z; sq4.w += acc.w * acc.w;
    }
    int c = lane * 4;
    atomicAdd(&ss[c + 0], sum4.x); atomicAdd(&ss[c + 1], sum4.y);
    atomicAdd(&ss[c + 2], sum4.z); atomicAdd(&ss[c + 3], sum4.w);
    atomicAdd(&sq[c + 0], sq4.x);  atomicAdd(&sq[c + 1], sq4.y);
    atomicAdd(&sq[c + 2], sq4.z);  atomicAdd(&sq[c + 3], sq4.w);
    __syncthreads();
    if (t < 128) {
        atomicAdd(&d_stats[t], ss[t]);
        atomicAdd(&d_stats[128 + t], sq[t]);
    }
    __threadfence();
    if (t == 0) s_last = (atomicAdd(&d_ctr, 1) == (int)gridDim.x - 1) ? 1 : 0;
    __syncthreads();
    if (s_last) {
        __threadfence();
        if (t < 128) {
            float m = d_stats[t] * (1.0f / NN);
            float v = d_stats[128 + t] * (1.0f / NN) - m * m;
            float sc = gamma[t] * rsqrtf(v + 1e-5f);
            d_scale[t] = sc;
            d_shift[t] = beta[t] - m * sc;
            d_stats[t] = 0.f;
            d_stats[128 + t] = 0.f;
        }
        if (t == 0) d_ctr = 0;
    }
}

// ---------------- fused BN-apply + pooling (final GCN layer) ----------------
__global__ __launch_bounds__(256) void k_bnpool(const void* __restrict__ batch) {
    int n = blockIdx.x * 8 + (threadIdx.x >> 5);
    if (n >= NN) return;
    int lane = threadIdx.x & 31;
    int g;
    if (d_is64) g = (int)((const long long*)batch)[n];
    else        g = ((const int*)batch)[n];
    g = min(max(g, 0), GG - 1);
    int c = lane * 4;
    float4 sc = *(const float4*)&d_scale[c];
    float4 sh = *(const float4*)&d_shift[c];
    float4 v = *((const float4*)(d_agg + (size_t)n * 128) + lane);
    v.x = fmaxf(v.x * sc.x + sh.x, 0.f);
    v.y = fmaxf(v.y * sc.y + sh.y, 0.f);
    v.z = fmaxf(v.z * sc.z + sh.z, 0.f);
    v.w = fmaxf(v.w * sc.w + sh.w, 0.f);
    red_add_v4(d_hp + (size_t)g * 128 + c, v.x, v.y, v.z, v.w);
}

// ---------------- head layer 0: l0 = relu(hp @ Wl0 + bl0) ----------------
__global__ __launch_bounds__(256) void k_head0(const float* __restrict__ W, const float* __restrict__ b) {
    __shared__ float in_s[8 * 128];
    int t = threadIdx.x;
    int g0 = blockIdx.x * 8;
    for (int i = t; i < (8 * 128) / 4; i += 256)
        ((float4*)in_s)[i] = ((const float4*)(d_hp + (size_t)g0 * 128))[i];
    __syncthreads();
    float acc[8] = {};
    for (int k = 0; k < 128; k++) {
        float w = W[k * 256 + t];
        #pragma unroll
        for (int r = 0; r < 8; r++) acc[r] += in_s[r * 128 + k] * w;
    }
    float bb = b[t];
    #pragma unroll
    for (int r = 0; r < 8; r++)
        d_l0[(size_t)(g0 + r) * 256 + t] = fmaxf(acc[r] + bb, 0.0f);
}

// ---------------- head GEMM: out = f(in) @ W + b, with fused BN stats + finalize ----------------
template <bool INBN>
__global__ __launch_bounds__(256) void k_headgemm(const float* __restrict__ in,
                                                  const float* __restrict__ W,
                                                  const float* __restrict__ b,
                                                  float* __restrict__ out,
                                                  const float* __restrict__ gamma,
                                                  const float* __restrict__ beta) {
    __shared__ float in_s[8 * 256];
    __shared__ int s_last;
    int t = threadIdx.x;
    int g0 = blockIdx.x * 8;
    for (int i = t; i < 512; i += 256) {
        float4 v = ((const float4*)(in + (size_t)g0 * 256))[i];
        if (INBN) {
            int c = (i * 4) & 255;
            float4 sc = *(const float4*)&d_lscale[c];
            float4 sh = *(const float4*)&d_lshift[c];
            v.x = fmaxf(v.x * sc.x + sh.x, 0.f);
            v.y = fmaxf(v.y * sc.y + sh.y, 0.f);
            v.z = fmaxf(v.z * sc.z + sh.z, 0.f);
            v.w = fmaxf(v.w * sc.w + sh.w, 0.f);
        }
        ((float4*)in_s)[i] = v;
    }
    __syncthreads();
    float acc[8] = {};
    for (int k = 0; k < 256; k++) {
        float w = W[k * 256 + t];
        #pragma unroll
        for (int r = 0; r < 8; r++) acc[r] += in_s[r * 256 + k] * w;
    }
    float bb = b[t];
    float ls = 0.f, lss = 0.f;
    #pragma unroll
    for (int r = 0; r < 8; r++) {
        float o = acc[r] + bb;
        out[(size_t)(g0 + r) * 256 + t] = o;
        ls += o; lss += o * o;
    }
    atomicAdd(&d_lstats[t], ls);
    atomicAdd(&d_lstats[256 + t], lss);
    __threadfence();
    if (t == 0) s_last = (atomicAdd(&d_lctr, 1) == (int)gridDim.x - 1) ? 1 : 0;
    __syncthreads();
    if (s_last) {
        __threadfence();
        float m = d_lstats[t] * (1.0f / GG);
        float v = d_lstats[256 + t] * (1.0f / GG) - m * m;
        float sc = gamma[t] * rsqrtf(v + 1e-5f);
        d_lscale[t] = sc;
        d_lshift[t] = beta[t] - m * sc;
        d_lstats[t] = 0.f;
        d_lstats[256 + t] = 0.f;
        if (t == 0) d_lctr = 0;
    }
}

// ---------------- final: out = relu(bn(in)) @ Wout + bout ----------------
__global__ __launch_bounds__(64) void k_final(const float* __restrict__ in,
                                              const float* __restrict__ Wout,
                                              const float* __restrict__ bout,
                                              float* __restrict__ out) {
    int r = blockIdx.x;
    int warp = threadIdx.x >> 5;
    int lane = threadIdx.x & 31;
    float s = 0.f;
    for (int k = lane; k < 256; k += 32) {
        float v = fmaxf(in[(size_t)r * 256 + k] * d_lscale[k] + d_lshift[k], 0.f);
        s += v * Wout[k * 2 + warp];
    }
    #pragma unroll
    for (int o = 16; o > 0; o >>= 1) s += __shfl_down_sync(0xffffffffu, s, o);
    if (lane == 0) out[r * 2 + warp] = s + bout[warp];
}

// ---------------- launch ----------------
extern "C" void kernel_launch(void* const* d_in, const int* in_sizes, int n_in,
                              void* d_out, int out_size) {
    const float* x     = (const float*)d_in[0];
    const void*  ei    = d_in[1];
    const void*  batch = d_in[2];
    int base = (n_in >= 18) ? 4 : 3;
    const float* W0      = (const float*)d_in[base + 0];
    const float* b0      = (const float*)d_in[base + 1];
    const float* Wg      = (const float*)d_in[base + 2];
    const float* bg      = (const float*)d_in[base + 3];
    const float* gamma_g = (const float*)d_in[base + 4];
    const float* beta_g  = (const float*)d_in[base + 5];
    const float* Wl0     = (const float*)d_in[base + 6];
    const float* bl0     = (const float*)d_in[base + 7];
    const float* Wl      = (const float*)d_in[base + 8];
    const float* bl      = (const float*)d_in[base + 9];
    const float* gamma_l = (const float*)d_in[base + 10];
    const float* beta_l  = (const float*)d_in[base + 11];
    const float* Wout    = (const float*)d_in[base + 12];
    const float* bout    = (const float*)d_in[base + 13];

    void *p_agg, *p_hw, *p_aggx, *p_l0, *p_l1;
    cudaGetSymbolAddress(&p_agg, d_agg);
    cudaGetSymbolAddress(&p_hw, d_hw);
    cudaGetSymbolAddress(&p_aggx, d_aggx);
    cudaGetSymbolAddress(&p_l0, d_l0);
    cudaGetSymbolAddress(&p_l1, d_l1);

    const int SMEM = (32 * 128 * 2 + 64 * 64) * 4;   // 48 KB (wt + hs)
    cudaFuncSetAttribute(k_gemm<64,  false, true>,  cudaFuncAttributeMaxDynamicSharedMemorySize, SMEM);
    cudaFuncSetAttribute(k_gemm<128, false, false>, cudaFuncAttributeMaxDynamicSharedMemorySize, SMEM);
    cudaFuncSetAttribute(k_gemm<128, true,  false>, cudaFuncAttributeMaxDynamicSharedMemorySize, SMEM);

    const int GEMM_GRID = (NN + 63) / 64;   // 782

    // preprocessing (4 kernels)
    k_prep<<<2500, 256>>>(ei);
    k_scan1<<<NBLK, 256>>>();
    k_scan3<<<NBLK, 256>>>();
    k_csr_fill<<<2500, 256>>>();

    // layer 0: aggregate raw x (64-wide), GEMM with bias+relu epilogue -> h (fp32) in d_agg
    k_aggx<<<6250, 256>>>(x);
    k_gemm<64, false, true><<<GEMM_GRID, 256, SMEM>>>((const float*)p_aggx, W0, b0, (float*)p_agg);

    // layers 1..4 (GCN; BN params via k_agg last-block finalize,
    // applied lazily in the next consumer's input load)
    for (int i = 0; i < GD_; i++) {
        if (i == 0)
            k_gemm<128, false, false><<<GEMM_GRID, 256, SMEM>>>((const float*)p_agg, Wg, nullptr, (float*)p_hw);
        else
            k_gemm<128, true, false><<<GEMM_GRID, 256, SMEM>>>((const float*)p_agg,
                                                               Wg + (size_t)i * 128 * 128, nullptr, (float*)p_hw);
        k_agg<<<782, 256>>>(bg + (size_t)i * 128,
                            gamma_g + (size_t)i * 128, beta_g + (size_t)i * 128);
    }

    // fused BN-apply + pooling (hp zeroed in k_scan1)
    k_bnpool<<<6250, 256>>>(batch);

    // head
    k_head0<<<128, 256>>>(Wl0, bl0);
    k_headgemm<false><<<128, 256>>>((const float*)p_l0, Wl, bl, (float*)p_l1,
                                    gamma_l, beta_l);
    k_headgemm<true><<<128, 256>>>((const float*)p_l1, Wl + (size_t)256 * 256, bl + 256, (float*)p_l0,
                                   gamma_l + 256, beta_l + 256);
    k_final<<<1024, 64>>>((const float*)p_l0, Wout, bout, (float*)d_out);
}